// round 9
// baseline (speedup 1.0000x reference)
#include <cuda_runtime.h>
#include <cstdint>

#define DD 128
#define KK 32
#define NTHREADS 512
#define NBLOCKS 444
#define NCELLS 128

// ---- shared memory layout ----
// Dim slots are swizzled: logical dim d lives at slot sd = (d&3)*32 + (d>>2),
// so a lane owning logical dims 4*lane..4*lane+3 touches slots 32*i + lane
// -> bank = lane, conflict-free for every table at any bin index.
// s_x  : float [33][128]  knot x positions (scalar, LDS.32)
// s_ys : float2[33][128]  {y_k, slope_k}
// s_lut: uint8 [128][128] bin base per cell, pre-clamped to <= 27
#define XS_OFF 0
#define YS_F2_OFF (33 * DD / 2)              // float2 index into sm
#define LUT_BYTE_OFF ((33 * DD + 2 * 33 * DD) * 4)
#define SMEM_BYTES (LUT_BYTE_OFF + NCELLS * DD)

__global__ void __launch_bounds__(NTHREADS, 3)
rqs_kernel(const float* __restrict__ x,
           const float* __restrict__ sp,
           float* __restrict__ y_out,
           float* __restrict__ ld_out,
           int n_rows)
{
    extern __shared__ float sm[];
    float*   s_x   = sm + XS_OFF;
    float2*  s_ys  = (float2*)sm + YS_F2_OFF;
    uint8_t* s_lut = (uint8_t*)sm + LUT_BYTE_OFF;

    const int tid = threadIdx.x;
    const float TOTAL_M = 10.0f - KK * 1e-4f;

    // ---- per-block table build (redundant across blocks, trivially cheap) ----
    if (tid < DD) {
        const int d = tid;
        const int sd = (d & 3) * 32 + (d >> 2);        // swizzled slot
        const float* uw = sp + d * (3 * KK + 1);
        float m = -1e30f;
        #pragma unroll 1
        for (int k = 0; k < KK; k++) m = fmaxf(m, uw[k]);
        float s = 0.f;
        #pragma unroll 1
        for (int k = 0; k < KK; k++) s += __expf(uw[k] - m);
        float scale = TOTAL_M / s;
        float run = -5.0f;
        s_x[sd] = run;
        #pragma unroll 1
        for (int k = 0; k < KK; k++) {
            float w = __expf(uw[k] - m) * scale + 1e-4f;
            run += w;
            s_x[(k + 1) * DD + sd] = run;
        }
        // LUT: bin of each cell's left edge, clamped so base+4 <= 31
        int k = 0;
        #pragma unroll 1
        for (int c = 0; c < NCELLS; c++) {
            float cl = c * 0.078125f - 5.0f;   // exact: 10/128
            while (k < 31 && s_x[(k + 1) * DD + sd] <= cl) k++;
            s_lut[c * DD + sd] = (uint8_t)min(k, 27);
        }
    } else if (tid < 2 * DD) {
        const int d = tid - DD;
        const int sd = (d & 3) * 32 + (d >> 2);
        const float* uh = sp + d * (3 * KK + 1) + KK;
        const float* us = sp + d * (3 * KK + 1) + 2 * KK;
        float m = -1e30f;
        #pragma unroll 1
        for (int k = 0; k < KK; k++) m = fmaxf(m, uh[k]);
        float s = 0.f;
        #pragma unroll 1
        for (int k = 0; k < KK; k++) s += __expf(uh[k] - m);
        float scale = TOTAL_M / s;
        const float OFFS = 0.5411666430f;  // log(expm1(1 - 1e-4))
        float run = -5.0f;
        #pragma unroll 1
        for (int k = 0; k <= KK; k++) {
            float v = us[k] + OFFS;
            float spv = fmaxf(v, 0.f) + __logf(1.f + __expf(-fabsf(v)));
            s_ys[k * DD + sd] = make_float2(run, spv + 1e-4f);
            if (k < KK) run += __expf(uh[k] - m) * scale + 1e-4f;
        }
    }
    __syncthreads();

    // ---- main loop: one warp per row; lane owns logical dims 4*lane+i ----
    const int lane = tid & 31;
    const int warp = (blockIdx.x * NTHREADS + tid) >> 5;
    const int nwarps = gridDim.x * (NTHREADS >> 5);
    const float LN2 = 0.69314718055994531f;

    for (int row = warp; row < n_rows; row += nwarps) {
        const float4 xin = *(const float4*)(x + (unsigned)row * DD + 4 * lane);
        const float xa[4] = {xin.x, xin.y, xin.z, xin.w};
        float yv[4];
        float prod = 1.0f;

        #pragma unroll
        for (int i = 0; i < 4; i++) {
            const int slot = 32 * i + lane;
            const float xv = xa[i];

            // LUT: conservative (low) bin base, pre-clamped at build
            int c = (int)fmaf(xv, 12.8f, 63.0f);   // floor((xv+5)*12.8) - 1
            c = max(0, min(c, NCELLS - 1));
            const int base = (int)s_lut[c * DD + slot];

            // 4 branchless indicator loads (conflict-free LDS.32, imm offsets)
            const float* xb = s_x + base * DD + slot;
            const int idx = base + (xv >= xb[1 * DD]) + (xv >= xb[2 * DD])
                                 + (xv >= xb[3 * DD]) + (xv >= xb[4 * DD]);

            // fetch (all parallel, conflict-free)
            const int o = idx * DD + slot;
            const float  x0 = s_x[o];
            const float  x1 = s_x[o + DD];
            const float2 r0 = s_ys[o];
            const float2 r1 = s_ys[o + DD];
            const float y0 = r0.x, s0 = r0.y;
            const float y1 = r1.x, s1 = r1.y;

            // branchless boundary: clamp x into the bin, remember the excess
            const float xc = fminf(fmaxf(xv, x0), x1);
            const float e  = xv - xc;                   // 0 when interior

            float ib;
            asm("rcp.approx.f32 %0, %1;" : "=f"(ib) : "f"(x1 - x0));
            const float z    = fminf((xc - x0) * ib, 1.0f);
            const float bh   = y1 - y0;
            const float bs   = bh * ib;
            const float sqz  = z * z;
            const float z1mz = z - sqz;
            const float omz  = 1.f - z;
            const float sq1  = omz * omz;

            const float st  = (s0 + s1) - 2.f * bs;
            const float den = fmaf(st, z1mz, bs);
            const float num = bh * fmaf(s0, z1mz, bs * sqz);

            float r;
            asm("rcp.approx.f32 %0, %1;" : "=f"(r) : "f"(den));

            // interior value; at z==0/1 this is exactly y0 / ~y1, so the
            // linear tail is just +e*s_edge
            const float s_edge = (xv < x0) ? s0 : s1;
            const float yy = fmaf(e, s_edge, fmaf(num, r, y0));

            // deriv = bs^2 * arg / den^2 (interior), s_edge outside
            const float arg = fmaf(s1, sqz, fmaf(s0, sq1, (bs + bs) * z1mz));
            const float t   = bs * r;
            const float deriv = (e != 0.0f) ? s_edge : (t * t) * arg;

            prod *= deriv;
            yv[i] = yy;
        }

        *(float4*)(y_out + (unsigned)row * DD + 4 * lane) =
            make_float4(yv[0], yv[1], yv[2], yv[3]);

        // one LG2 per 4 elements, then warp-sum; scale by ln2 once per row
        float ls = __log2f(prod);
        #pragma unroll
        for (int off = 16; off; off >>= 1)
            ls += __shfl_xor_sync(0xffffffffu, ls, off);
        if (lane == 0) ld_out[row] = ls * LN2;
    }
}

extern "C" void kernel_launch(void* const* d_in, const int* in_sizes, int n_in,
                              void* d_out, int out_size)
{
    const float* x  = (const float*)d_in[0];
    const float* sp = (const float*)d_in[1];
    const int n_rows = in_sizes[0] / DD;

    float* y_out  = (float*)d_out;
    float* ld_out = (float*)d_out + (size_t)n_rows * DD;

    cudaFuncSetAttribute(rqs_kernel, cudaFuncAttributeMaxDynamicSharedMemorySize,
                         SMEM_BYTES);
    rqs_kernel<<<NBLOCKS, NTHREADS, SMEM_BYTES>>>(x, sp, y_out, ld_out, n_rows);
}

// round 10
// speedup vs baseline: 1.0802x; 1.0802x over previous
#include <cuda_runtime.h>
#include <cstdint>

#define DD 128
#define KK 32
#define NTHREADS 512
#define NBLOCKS 444
#define NCELLS 64

// ---- shared memory layout ----
// Dim slots swizzled: logical dim d -> slot sd = (d&3)*32 + (d>>2), so a lane
// owning logical dims 4*lane..4*lane+3 touches slots 32*i+lane (bank = lane).
// s_xib : float2[33][128] {x_k, 1/(x_{k+1}-x_k)}   (LDS.64, 2-phase cf)
// s_ys  : float2[33][128] {y_k, slope_k}
// s_lutw: uint32[16][128] 4 packed cell-bases per word, dim-stride 4B
//         -> LUT fetch is ONE conflict-free LDS.32 (byte layouts are 4-way
//            conflicted; this was a hidden cost in rounds 4-9).
#define SMEM_BYTES (2 * (33 * DD * 8) + (NCELLS / 4) * DD * 4)

__global__ void __launch_bounds__(NTHREADS, 3)
rqs_kernel(const float* __restrict__ x,
           const float* __restrict__ sp,
           float* __restrict__ y_out,
           float* __restrict__ ld_out,
           int n_rows)
{
    extern __shared__ float sm[];
    float2*   s_xib  = (float2*)sm;
    float2*   s_ys   = s_xib + 33 * DD;
    uint32_t* s_lutw = (uint32_t*)(s_ys + 33 * DD);

    const int tid = threadIdx.x;
    const float TOTAL_M = 10.0f - KK * 1e-4f;

    // ---- per-block table build (redundant across blocks, trivially cheap) ----
    if (tid < DD) {
        const int d = tid;
        const int sd = (d & 3) * 32 + (d >> 2);        // swizzled slot
        const float* uw = sp + d * (3 * KK + 1);
        float m = -1e30f;
        #pragma unroll 1
        for (int k = 0; k < KK; k++) m = fmaxf(m, uw[k]);
        float s = 0.f;
        #pragma unroll 1
        for (int k = 0; k < KK; k++) s += __expf(uw[k] - m);
        float scale = TOTAL_M / s;
        float run = -5.0f;
        #pragma unroll 1
        for (int k = 0; k < KK; k++) {
            float w = __expf(uw[k] - m) * scale + 1e-4f;
            float nxt = run + w;
            s_xib[k * DD + sd] = make_float2(run, 1.0f / (nxt - run));
            run = nxt;
        }
        s_xib[KK * DD + sd] = make_float2(run, 0.0f);   // x_32 (~5.0)
        // LUT: bin of each cell's left edge (clamped to 29), 4 cells per word
        int k = 0;
        uint32_t word = 0;
        #pragma unroll 1
        for (int c = 0; c < NCELLS; c++) {
            float cl = c * 0.15625f - 5.0f;             // exact: 10/64
            while (k < 31 && s_xib[(k + 1) * DD + sd].x <= cl) k++;
            word |= (uint32_t)min(k, 29) << ((c & 3) * 8);
            if ((c & 3) == 3) { s_lutw[(c >> 2) * DD + sd] = word; word = 0; }
        }
    } else if (tid < 2 * DD) {
        const int d = tid - DD;
        const int sd = (d & 3) * 32 + (d >> 2);
        const float* uh = sp + d * (3 * KK + 1) + KK;
        const float* us = sp + d * (3 * KK + 1) + 2 * KK;
        float m = -1e30f;
        #pragma unroll 1
        for (int k = 0; k < KK; k++) m = fmaxf(m, uh[k]);
        float s = 0.f;
        #pragma unroll 1
        for (int k = 0; k < KK; k++) s += __expf(uh[k] - m);
        float scale = TOTAL_M / s;
        const float OFFS = 0.5411666430f;  // log(expm1(1 - 1e-4))
        float run = -5.0f;
        #pragma unroll 1
        for (int k = 0; k <= KK; k++) {
            float v = us[k] + OFFS;
            float spv = fmaxf(v, 0.f) + __logf(1.f + __expf(-fabsf(v)));
            s_ys[k * DD + sd] = make_float2(run, spv + 1e-4f);
            if (k < KK) run += __expf(uh[k] - m) * scale + 1e-4f;
        }
    }
    __syncthreads();

    // ---- main loop: one warp per row; lane owns logical dims 4*lane+i ----
    const int lane = tid & 31;
    const int warp = (blockIdx.x * NTHREADS + tid) >> 5;
    const int nwarps = gridDim.x * (NTHREADS >> 5);
    const float LN2 = 0.69314718055994531f;

    for (int row = warp; row < n_rows; row += nwarps) {
        const float4 xin = *(const float4*)(x + (unsigned)row * DD + 4 * lane);
        const float xa[4] = {xin.x, xin.y, xin.z, xin.w};
        float yv[4];
        float prod = 1.0f;

        #pragma unroll
        for (int i = 0; i < 4; i++) {
            const int slot = 32 * i + lane;
            const float xv = xa[i];

            // LUT (1 conflict-free LDS.32): conservative (low) bin base
            const int c = (int)fminf(fmaxf(fmaf(xv, 6.4f, 31.0f), 0.0f), 63.0f);
            const uint32_t w = s_lutw[(c >> 2) * DD + slot];
            const int base = (int)((w >> ((c & 3) * 8)) & 0xFF);

            // 2 indicator loads refine; predicated adds build the offset
            int o = base * DD + slot;
            const float k1 = s_xib[o + DD].x;
            const float k2 = s_xib[o + 2 * DD].x;
            if (xv >= k1) o += DD;
            if (xv >= k2) o += DD;

            // fetch {x0, ib}; rare fixup walks up (narrow bins / above-range)
            float2 xi = s_xib[o];
            float zr = (xv - xi.x) * xi.y;
            while (zr > 1.0f && o < (KK - 1) * DD) {   // cold
                o += DD;
                xi = s_xib[o];
                zr = (xv - xi.x) * xi.y;
            }
            const float2 r0 = s_ys[o];
            const float2 r1 = s_ys[o + DD];
            const float y0 = r0.x, s0 = r0.y;
            const float y1 = r1.x, s1 = r1.y;
            const float ib = xi.y;

            const float z    = fminf(fmaxf(zr, 0.f), 1.f);
            const float bh   = y1 - y0;
            const float bs   = bh * ib;
            const float sqz  = z * z;
            const float z1mz = z - sqz;
            const float omz  = 1.f - z;
            const float sq1  = omz * omz;

            const float st  = (s0 + s1) - 2.f * bs;
            const float den = fmaf(st, z1mz, bs);
            const float num = bh * fmaf(s0, z1mz, bs * sqz);

            float r;
            asm("rcp.approx.f32 %0, %1;" : "=f"(r) : "f"(den));
            float yy = fmaf(num, r, y0);

            // deriv = bs^2 * arg / den^2 ; fold bs^2 via t = bs * (1/den)
            const float arg = fmaf(s1, sqz, fmaf(s0, sq1, (bs + bs) * z1mz));
            const float t   = bs * r;
            float deriv = (t * t) * arg;

            // out-of-range tails (P ~ 6e-7): rare branch, not branchless
            if (zr != z) {
                if (zr < 0.f) {
                    yy = fmaf(xv - xi.x, s0, y0);
                    deriv = s0;
                } else {
                    const float x1 = s_xib[o + DD].x;
                    yy = fmaf(xv - x1, s1, y1);
                    deriv = s1;
                }
            }
            prod *= deriv;
            yv[i] = yy;
        }

        *(float4*)(y_out + (unsigned)row * DD + 4 * lane) =
            make_float4(yv[0], yv[1], yv[2], yv[3]);

        // one LG2 per 4 elements, then warp-sum; scale by ln2 once per row
        float ls = __log2f(prod);
        #pragma unroll
        for (int off = 16; off; off >>= 1)
            ls += __shfl_xor_sync(0xffffffffu, ls, off);
        if (lane == 0) ld_out[row] = ls * LN2;
    }
}

extern "C" void kernel_launch(void* const* d_in, const int* in_sizes, int n_in,
                              void* d_out, int out_size)
{
    const float* x  = (const float*)d_in[0];
    const float* sp = (const float*)d_in[1];
    const int n_rows = in_sizes[0] / DD;

    float* y_out  = (float*)d_out;
    float* ld_out = (float*)d_out + (size_t)n_rows * DD;

    cudaFuncSetAttribute(rqs_kernel, cudaFuncAttributeMaxDynamicSharedMemorySize,
                         SMEM_BYTES);
    rqs_kernel<<<NBLOCKS, NTHREADS, SMEM_BYTES>>>(x, sp, y_out, ld_out, n_rows);
}